// round 5
// baseline (speedup 1.0000x reference)
#include <cuda_runtime.h>

// B=4, H=8, S=2048, D=3 (fixed by reference)
typedef unsigned long long u64;

#define S_LEN   2048
#define QPC     64            // queries per CTA
#define THREADS 128           // 4 key-groups x 32 threads; 2 queries per thread
#define N_CTA   1024          // 32 bh * 32 chunks
#define KPG     512           // keys per group
#define QUADS   (KPG / 4)     // 128 iterations
#define OUT_HALF (32 * S_LEN * 3)

// smem (floats): x quads 512*12 = 6144 ; wmax 16.  red (1024 floats) aliases sm[0..1023].
#define SM_WMAX   6144
#define SMEM_BYTES ((6144 + 16) * 4)   // 24640 B

__device__ __forceinline__ u64 fma2(u64 a, u64 b, u64 c) {
    u64 d; asm("fma.rn.f32x2 %0, %1, %2, %3;" : "=l"(d) : "l"(a), "l"(b), "l"(c));
    return d;
}
__device__ __forceinline__ u64 add2(u64 a, u64 b) {
    u64 d; asm("add.rn.f32x2 %0, %1, %2;" : "=l"(d) : "l"(a), "l"(b));
    return d;
}
__device__ __forceinline__ u64 ex2_2(u64 x) {
    u64 r;
    asm("{\n\t"
        ".reg .f32 lo, hi;\n\t"
        "mov.b64 {lo, hi}, %1;\n\t"
        "ex2.approx.f32 lo, lo;\n\t"
        "ex2.approx.f32 hi, hi;\n\t"
        "mov.b64 %0, {lo, hi};\n\t"
        "}" : "=l"(r) : "l"(x));
    return r;
}
__device__ __forceinline__ u64 pack2(float lo, float hi) {
    u64 r; asm("mov.b64 %0, {%1, %2};" : "=l"(r) : "f"(lo), "f"(hi));
    return r;
}
__device__ __forceinline__ void unpack2(u64 v, float& lo, float& hi) {
    asm("mov.b64 {%0, %1}, %2;" : "=f"(lo), "=f"(hi) : "l"(v));
}
__device__ __forceinline__ float rcpa(float x) {
    float r; asm("rcp.approx.f32 %0, %1;" : "=f"(r) : "f"(x));
    return r;
}
// LDS.128 -> two u64 halves, 32-bit shared address
__device__ __forceinline__ void ld2(u64& a, u64& b, unsigned addr) {
    asm("ld.shared.v2.b64 {%0, %1}, [%2];" : "=l"(a), "=l"(b) : "r"(addr));
}

// one 4-key step for one query
__device__ __forceinline__ void step(u64 q0p, u64 q1p, u64 q2p, u64 nm,
                                     u64 X0a, u64 X0b, u64 X1a, u64 X1b,
                                     u64 X2a, u64 X2b,
                                     u64& l, u64& t0, u64& t1, u64& t2)
{
    const u64 dA = fma2(q0p, X0a, fma2(q1p, X1a, fma2(q2p, X2a, nm)));
    const u64 dB = fma2(q0p, X0b, fma2(q1p, X1b, fma2(q2p, X2b, nm)));
    const u64 pA = ex2_2(dA);
    const u64 pB = ex2_2(dB);
    l  = add2(l, add2(pA, pB));
    t0 = fma2(pA, X0a, fma2(pB, X0b, t0));
    t1 = fma2(pA, X1a, fma2(pB, X1b, t1));
    t2 = fma2(pA, X2a, fma2(pB, X2b, t2));
}

__global__ __launch_bounds__(THREADS, 7)
void attn3d_kernel(const float* __restrict__ x,
                   const float* __restrict__ Wq,
                   const float* __restrict__ Wk,
                   const float* __restrict__ Wv,
                   float* __restrict__ out)
{
    extern __shared__ float sm[];
    float* red  = sm;             // aliases x region (valid after post-loop barrier)
    float* wmax = sm + SM_WMAX;

    const int tid   = threadIdx.x;
    const int cta   = blockIdx.x;
    const int bh    = cta >> 5;
    const int chunk = cta & 31;
    const int b     = bh >> 3;
    const int h     = bh & 7;

    const float* xb = x + (size_t)b * S_LEN * 3;

    // ---- Fill smem with raw x (quad-packed SoA) + per-component max|x| ----
    float M0 = 0.f, M1 = 0.f, M2 = 0.f;
    #pragma unroll
    for (int i = 0; i < S_LEN / THREADS; ++i) {
        const int k = tid + i * THREADS;
        const float x0 = xb[k * 3 + 0];
        const float x1 = xb[k * 3 + 1];
        const float x2 = xb[k * 3 + 2];
        const int j = k >> 2, c = k & 3;
        sm[j * 12 + 0 + c] = x0;
        sm[j * 12 + 4 + c] = x1;
        sm[j * 12 + 8 + c] = x2;
        M0 = fmaxf(M0, fabsf(x0));
        M1 = fmaxf(M1, fabsf(x1));
        M2 = fmaxf(M2, fabsf(x2));
    }
    unsigned u0 = __reduce_max_sync(0xffffffffu, __float_as_uint(M0));
    unsigned u1 = __reduce_max_sync(0xffffffffu, __float_as_uint(M1));
    unsigned u2 = __reduce_max_sync(0xffffffffu, __float_as_uint(M2));
    if ((tid & 31) == 0) {
        const int w = tid >> 5;
        wmax[w * 3 + 0] = __uint_as_float(u0);
        wmax[w * 3 + 1] = __uint_as_float(u1);
        wmax[w * 3 + 2] = __uint_as_float(u2);
    }

    // ---- Two queries per thread ----
    const int g  = tid >> 5;           // key group 0..3
    const int ql = tid & 31;
    const float* wq = Wq + h * 9;
    const float* wk = Wk + h * 9;
    const float RS = 0.57735026918962576f * 1.4426950408889634f;

    float qt0[2], qt1[2], qt2[2];
    #pragma unroll
    for (int qq = 0; qq < 2; ++qq) {
        const int sq = chunk * QPC + ql + qq * 32;
        const float xq0 = xb[sq * 3 + 0];
        const float xq1 = xb[sq * 3 + 1];
        const float xq2 = xb[sq * 3 + 2];
        const float q0 = xq0 * wq[0] + xq1 * wq[3] + xq2 * wq[6];
        const float q1 = xq0 * wq[1] + xq1 * wq[4] + xq2 * wq[7];
        const float q2 = xq0 * wq[2] + xq1 * wq[5] + xq2 * wq[8];
        qt0[qq] = RS * (q0 * wk[0] + q1 * wk[1] + q2 * wk[2]);
        qt1[qq] = RS * (q0 * wk[3] + q1 * wk[4] + q2 * wk[5]);
        qt2[qq] = RS * (q0 * wk[6] + q1 * wk[7] + q2 * wk[8]);
    }

    __syncthreads();

    const float MM0 = fmaxf(fmaxf(wmax[0], wmax[3]), fmaxf(wmax[6], wmax[9]));
    const float MM1 = fmaxf(fmaxf(wmax[1], wmax[4]), fmaxf(wmax[7], wmax[10]));
    const float MM2 = fmaxf(fmaxf(wmax[2], wmax[5]), fmaxf(wmax[8], wmax[11]));

    u64 q0p[2], q1p[2], q2p[2], nm[2];
    #pragma unroll
    for (int qq = 0; qq < 2; ++qq) {
        const float m = fabsf(qt0[qq]) * MM0 + fabsf(qt1[qq]) * MM1
                      + fabsf(qt2[qq]) * MM2 + 1.0f;
        q0p[qq] = pack2(qt0[qq], qt0[qq]);
        q1p[qq] = pack2(qt1[qq], qt1[qq]);
        q2p[qq] = pack2(qt2[qq], qt2[qq]);
        nm[qq]  = pack2(-m, -m);
    }

    // 32-bit shared-space base address for this key group
    unsigned sbase;
    asm("{ .reg .u64 t; cvta.to.shared.u64 t, %1; cvt.u32.u64 %0, t; }"
        : "=r"(sbase) : "l"(sm));
    unsigned p = sbase + g * (QUADS * 48);   // 48 B per quad record

    // ---- Software-pipelined inner loop: 128 quads, 1-iter lookahead ----
    u64 lacc[2] = {0ull, 0ull};
    u64 t0[2] = {0ull, 0ull}, t1[2] = {0ull, 0ull}, t2[2] = {0ull, 0ull};

    u64 x0a, x0b, x1a, x1b, x2a, x2b;
    ld2(x0a, x0b, p + 0);
    ld2(x1a, x1b, p + 16);
    ld2(x2a, x2b, p + 32);

    #pragma unroll 2
    for (int j = 0; j < QUADS - 1; ++j) {
        u64 y0a, y0b, y1a, y1b, y2a, y2b;
        ld2(y0a, y0b, p + 48);
        ld2(y1a, y1b, p + 64);
        ld2(y2a, y2b, p + 80);
        p += 48;
        step(q0p[0], q1p[0], q2p[0], nm[0], x0a, x0b, x1a, x1b, x2a, x2b,
             lacc[0], t0[0], t1[0], t2[0]);
        step(q0p[1], q1p[1], q2p[1], nm[1], x0a, x0b, x1a, x1b, x2a, x2b,
             lacc[1], t0[1], t1[1], t2[1]);
        x0a = y0a; x0b = y0b; x1a = y1a; x1b = y1b; x2a = y2a; x2b = y2b;
    }
    step(q0p[0], q1p[0], q2p[0], nm[0], x0a, x0b, x1a, x1b, x2a, x2b,
         lacc[0], t0[0], t1[0], t2[0]);
    step(q0p[1], q1p[1], q2p[1], nm[1], x0a, x0b, x1a, x1b, x2a, x2b,
         lacc[1], t0[1], t1[1], t2[1]);

    // ---- All warps done reading x; reuse smem for reduction ----
    __syncthreads();
    #pragma unroll
    for (int qq = 0; qq < 2; ++qq) {
        const int q = ql + qq * 32;
        float a, c;
        unpack2(lacc[qq], a, c); red[0 * 256 + g * 64 + q] = a + c;
        unpack2(t0[qq],   a, c); red[1 * 256 + g * 64 + q] = a + c;
        unpack2(t1[qq],   a, c); red[2 * 256 + g * 64 + q] = a + c;
        unpack2(t2[qq],   a, c); red[3 * 256 + g * 64 + q] = a + c;
    }
    __syncthreads();

    if (tid < QPC) {
        float L  = red[0 * 256 + tid] + red[0 * 256 + 64 + tid]
                 + red[0 * 256 + 128 + tid] + red[0 * 256 + 192 + tid];
        float T0 = red[1 * 256 + tid] + red[1 * 256 + 64 + tid]
                 + red[1 * 256 + 128 + tid] + red[1 * 256 + 192 + tid];
        float T1 = red[2 * 256 + tid] + red[2 * 256 + 64 + tid]
                 + red[2 * 256 + 128 + tid] + red[2 * 256 + 192 + tid];
        float T2 = red[3 * 256 + tid] + red[3 * 256 + 64 + tid]
                 + red[3 * 256 + 128 + tid] + red[3 * 256 + 192 + tid];
        const float inv = rcpa(L);
        const float* wv = Wv + h * 9;
        const float r0 = (T0 * wv[0] + T1 * wv[3] + T2 * wv[6]) * inv;
        const float r1 = (T0 * wv[1] + T1 * wv[4] + T2 * wv[7]) * inv;
        const float r2 = (T0 * wv[2] + T1 * wv[5] + T2 * wv[8]) * inv;
        const int base = (bh * S_LEN + chunk * QPC + tid) * 3;
        out[base + 0] = r0;
        out[base + 1] = r1;
        out[base + 2] = r2;
        out[OUT_HALF + base + 0] = r0;
        out[OUT_HALF + base + 1] = r1;
        out[OUT_HALF + base + 2] = r2;
    }
}

extern "C" void kernel_launch(void* const* d_in, const int* in_sizes, int n_in,
                              void* d_out, int out_size)
{
    const float* x  = (const float*)d_in[0];
    const float* Wq = (const float*)d_in[1];
    const float* Wk = (const float*)d_in[2];
    const float* Wv = (const float*)d_in[3];
    float* out = (float*)d_out;

    cudaFuncSetAttribute(attn3d_kernel,
                         cudaFuncAttributeMaxDynamicSharedMemorySize, SMEM_BYTES);
    attn3d_kernel<<<N_CTA, THREADS, SMEM_BYTES>>>(x, Wq, Wk, Wv, out);
}